// round 6
// baseline (speedup 1.0000x reference)
#include <cuda_runtime.h>
#include <cuda_bf16.h>
#include <cstdint>
#include <math.h>

#define NDIM 8192
#define RANK 64
#define BM 128
#define BKC 64
#define NCH (NDIM / BKC)       // 128 K-chunks
#define QTHREADS 512
#define ROWB 80                // padded fp8 row stride (conflict-free ldmatrix)
#define A_TILE (BM * ROWB)
#define B_TILE (RANK * ROWB)
#define QSMEM (1024 + 3 * (A_TILE + B_TILE))

// ---- device scratch (allocation-free rule) ----
__device__ double g_acc[3];                     // [0]=E1, [1]=quad_U, [2]=quad_V
__device__ float  g_Vt[NDIM * RANK];            // V^T fp32 [8192,64]
__device__ uint8_t g_Bu[RANK * NDIM];           // U^T e4m3 [64,8192] (MMA B)
__device__ uint8_t g_Bv[RANK * NDIM];           // V   e4m3 [64,8192] (MMA B)
__device__ __nv_bfloat16 g_Ub16[NDIM * RANK];   // U    bf16 [8192,64] (e1)
__device__ __nv_bfloat16 g_Vt16[NDIM * RANK];   // V^T  bf16 [8192,64] (e1)

__device__ __forceinline__ uint32_t smem_u32(const void* p) {
    uint32_t a;
    asm("{ .reg .u64 t; cvta.to.shared.u64 t, %1; cvt.u32.u64 %0, t; }"
        : "=r"(a) : "l"(p));
    return a;
}
__device__ __forceinline__ uint8_t f2e4m3(float f) {
    uint16_t v;
    asm("cvt.rn.satfinite.e4m3x2.f32 %0, %1, %2;" : "=h"(v) : "f"(0.f), "f"(f));
    return (uint8_t)v;   // low byte = second src
}

// ======================= prep (fused, grid.z selects) =======================
__global__ void prep_kernel(const float* __restrict__ V,
                            const float* __restrict__ U) {
    __shared__ float tile[32][33];
    if (blockIdx.z == 0) {
        int x = blockIdx.x * 32 + threadIdx.x;   // n
        int y = blockIdx.y * 32 + threadIdx.y;   // r
        float v = V[(size_t)y * NDIM + x];
        tile[threadIdx.y][threadIdx.x] = v;
        g_Bv[(size_t)y * NDIM + x] = f2e4m3(v);
        __syncthreads();
        int n = blockIdx.x * 32 + threadIdx.y;
        int r = blockIdx.y * 32 + threadIdx.x;
        float tv = tile[threadIdx.x][threadIdx.y];
        g_Vt[(size_t)n * RANK + r] = tv;
        g_Vt16[(size_t)n * RANK + r] = __float2bfloat16(tv);
        if (blockIdx.x == 0 && blockIdx.y == 0 && threadIdx.y == 0 &&
            threadIdx.x < 3)
            g_acc[threadIdx.x] = 0.0;
    } else {
        int i0 = blockIdx.x * 32, r0 = blockIdx.y * 32;
        float u = U[(size_t)(i0 + threadIdx.y) * RANK + r0 + threadIdx.x];
        tile[threadIdx.y][threadIdx.x] = u;
        g_Ub16[(size_t)(i0 + threadIdx.y) * RANK + r0 + threadIdx.x] =
            __float2bfloat16(u);
        __syncthreads();
        g_Bu[(size_t)(r0 + threadIdx.y) * NDIM + i0 + threadIdx.x] =
            f2e4m3(tile[threadIdx.x][threadIdx.y]);
    }
}

// ======================= fused quad (QMMA e4m3) + e1 =======================
// 512 threads, 16 warps: wm = wid&7 -> M rows wm*16..+15, wn = wid>>3 ->
// N half wn*32..+31. fp8 m16n8k32 MMA, 2-chunk register prefetch, 3 buffers.
__global__ __launch_bounds__(QTHREADS, 1) void fused_kernel(
    const float* __restrict__ S_U, const float* __restrict__ U,
    const float* __restrict__ S_V, const float* __restrict__ vals,
    const int* __restrict__ rows, const int* __restrict__ cols, int nobs) {
    extern __shared__ char dynsmem[];
    __shared__ float wsum[QTHREADS / 32];
    __shared__ float esum[QTHREADS / 32];

    const int t = threadIdx.x;
    const int wid = t >> 5, lane = t & 31;
    const int wm = wid & 7, wn = wid >> 3;

    const float* S;
    const uint8_t* Bg;
    const float* Xf;
    int slot;
    if (blockIdx.z == 0) { S = S_U; Bg = g_Bu; Xf = U;    slot = 1; }
    else                 { S = S_V; Bg = g_Bv; Xf = g_Vt; slot = 2; }
    const int i0 = blockIdx.x * BM;
    const int ctaid = blockIdx.x + 64 * blockIdx.z;   // 0..127

    uint32_t base = (smem_u32(dynsmem) + 1023u) & ~1023u;
    uint32_t bA = base;
    uint32_t bB = base + (A_TILE + B_TILE);
    uint32_t bC = base + 2 * (A_TILE + B_TILE);

    // staging: A 4 passes x 4 floats -> 4 fp8-bytes; B 1 pass x 8 fp8
    const float* a_base = S + (size_t)(i0 + (t >> 4)) * NDIM + (t & 15) * 4;
    const uint32_t a_st = (uint32_t)(t >> 4) * ROWB + (t & 15) * 4;
    const uint8_t* b_base = Bg + (size_t)(t >> 3) * NDIM + (t & 7) * 8;
    const uint32_t b_st = (uint32_t)(t >> 3) * ROWB + (t & 7) * 8;

    // ldmatrix lane offsets (fp8: 16B-quad layout identical to b16 path)
    const uint32_t a_lm = (uint32_t)(wm * 16 + (lane & 15)) * ROWB + (lane & 16);
    const uint32_t b_lm = (uint32_t)(wn * 32 + (lane & 15)) * ROWB + (lane & 16);

    float acc[4][4];
    #pragma unroll
    for (int tn = 0; tn < 4; tn++)
        #pragma unroll
        for (int q = 0; q < 4; q++) acc[tn][q] = 0.f;

    float e1sum = 0.f;
    float4 rAx[4], rAy[4];
    uint2  rBx, rBy;

#define LOADC(k0, RA, RB) do {                                                \
    _Pragma("unroll") for (int p = 0; p < 4; p++)                             \
        RA[p] = __ldcs((const float4*)(a_base + (k0) +                        \
                                       (size_t)p * 32 * NDIM));               \
    RB = *(const uint2*)(b_base + (k0));                                      \
} while (0)

#define STOREC(buf, RA, RB) do {                                              \
    _Pragma("unroll") for (int p = 0; p < 4; p++) {                           \
        uint16_t lo, hi;                                                      \
        asm("cvt.rn.satfinite.e4m3x2.f32 %0, %1, %2;" : "=h"(lo)              \
            : "f"(RA[p].y), "f"(RA[p].x));                                    \
        asm("cvt.rn.satfinite.e4m3x2.f32 %0, %1, %2;" : "=h"(hi)              \
            : "f"(RA[p].w), "f"(RA[p].z));                                    \
        uint32_t w = (uint32_t)lo | ((uint32_t)hi << 16);                     \
        asm volatile("st.shared.b32 [%0], %1;"                                \
                     :: "r"((buf) + a_st + p * (32 * ROWB)), "r"(w));         \
    }                                                                         \
    asm volatile("st.shared.v2.b32 [%0], {%1, %2};"                           \
                 :: "r"((buf) + A_TILE + b_st), "r"(RB.x), "r"(RB.y));        \
} while (0)

#define COMPUTE(buf) do {                                                     \
    uint32_t ab = (buf), bb = (buf) + A_TILE;                                 \
    _Pragma("unroll") for (int s = 0; s < 2; s++) {                           \
        uint32_t a[4];                                                        \
        asm volatile("ldmatrix.sync.aligned.m8n8.x4.shared.b16 "              \
                     "{%0,%1,%2,%3}, [%4];"                                   \
                     : "=r"(a[0]), "=r"(a[1]), "=r"(a[2]), "=r"(a[3])         \
                     : "r"(ab + a_lm + s * 32));                              \
        uint32_t b[2][4];                                                     \
        _Pragma("unroll") for (int j = 0; j < 2; j++)                         \
            asm volatile("ldmatrix.sync.aligned.m8n8.x4.shared.b16 "          \
                         "{%0,%1,%2,%3}, [%4];"                               \
                         : "=r"(b[j][0]), "=r"(b[j][1]),                      \
                           "=r"(b[j][2]), "=r"(b[j][3])                       \
                         : "r"(bb + b_lm + j * (16 * ROWB) + s * 32));        \
        _Pragma("unroll") for (int j = 0; j < 2; j++)                         \
            _Pragma("unroll") for (int h = 0; h < 2; h++) {                   \
                int tn = j * 2 + h;                                           \
                asm volatile(                                                 \
                    "mma.sync.aligned.m16n8k32.row.col.f32.e4m3.e4m3.f32 "    \
                    "{%0,%1,%2,%3}, {%4,%5,%6,%7}, {%8,%9}, {%0,%1,%2,%3};"   \
                    : "+f"(acc[tn][0]), "+f"(acc[tn][1]),                     \
                      "+f"(acc[tn][2]), "+f"(acc[tn][3])                      \
                    : "r"(a[0]), "r"(a[1]), "r"(a[2]), "r"(a[3]),             \
                      "r"(b[j][h]), "r"(b[j][h + 2]));                        \
            }                                                                 \
    }                                                                         \
} while (0)

#define E1_STEP(j) do {                                                       \
    int idx = ctaid * 8192 + (j) * QTHREADS + t;                              \
    if (idx < nobs) {                                                         \
        int r = rows[idx], c = cols[idx];                                     \
        float vv = vals[idx];                                                 \
        const uint4* u4 = (const uint4*)(g_Ub16 + (size_t)r * RANK);          \
        const uint4* v4 = (const uint4*)(g_Vt16 + (size_t)c * RANK);          \
        float s = 0.f;                                                        \
        _Pragma("unroll") for (int q = 0; q < 8; q++) {                       \
            uint4 ua = u4[q];                                                 \
            uint4 vb = v4[q];                                                 \
            const uint32_t* up = &ua.x;                                       \
            const uint32_t* vp = &vb.x;                                       \
            _Pragma("unroll") for (int h = 0; h < 4; h++) {                   \
                float2 fu = __bfloat1622float2(                               \
                    *(const __nv_bfloat162*)&up[h]);                          \
                float2 fv = __bfloat1622float2(                               \
                    *(const __nv_bfloat162*)&vp[h]);                          \
                s = fmaf(fu.x, fv.x, s);                                      \
                s = fmaf(fu.y, fv.y, s);                                      \
            }                                                                 \
        }                                                                     \
        float d = vv - s;                                                     \
        e1sum = fmaf(d, d, e1sum);                                            \
    }                                                                         \
} while (0)

    LOADC(0, rAx, rBx);
    LOADC(BKC, rAy, rBy);
    STOREC(bA, rAx, rBx);
    __syncthreads();

    for (int cc = 0; cc < NCH; cc += 2) {
        if (cc + 2 < NCH) LOADC((size_t)(cc + 2) * BKC, rAx, rBx);
        if ((cc & 7) == 0) E1_STEP(cc >> 3);     // 16 obs per thread
        COMPUTE(bA);
        STOREC(bB, rAy, rBy);
        __syncthreads();
        if (cc + 3 < NCH) LOADC((size_t)(cc + 3) * BKC, rAy, rBy);
        COMPUTE(bB);
        if (cc + 2 < NCH) STOREC(bC, rAx, rBx);
        __syncthreads();
        uint32_t tmp = bA; bA = bC; bC = bB; bB = tmp;
    }

    // quad epilogue: partial = sum of D[row][n] * X[row][n]
    const int g = lane >> 2, tg = lane & 3;
    const int r0 = i0 + wm * 16 + g;
    float partial = 0.f;
    #pragma unroll
    for (int tn = 0; tn < 4; tn++) {
        int n = wn * 32 + tn * 8 + 2 * tg;
        float2 x0 = *(const float2*)(Xf + (size_t)r0 * RANK + n);
        float2 x1 = *(const float2*)(Xf + (size_t)(r0 + 8) * RANK + n);
        partial = fmaf(acc[tn][0], x0.x, partial);
        partial = fmaf(acc[tn][1], x0.y, partial);
        partial = fmaf(acc[tn][2], x1.x, partial);
        partial = fmaf(acc[tn][3], x1.y, partial);
    }
    #pragma unroll
    for (int o = 16; o; o >>= 1) {
        partial += __shfl_xor_sync(0xffffffffu, partial, o);
        e1sum   += __shfl_xor_sync(0xffffffffu, e1sum, o);
    }
    if (lane == 0) { wsum[wid] = partial; esum[wid] = e1sum; }
    __syncthreads();
    if (t == 0) {
        float s = 0.f, e = 0.f;
        #pragma unroll
        for (int i = 0; i < QTHREADS / 32; i++) { s += wsum[i]; e += esum[i]; }
        atomicAdd(&g_acc[slot], (double)s);
        atomicAdd(&g_acc[0], (double)e);
    }
#undef LOADC
#undef STOREC
#undef COMPUTE
#undef E1_STEP
}

// ======================= finalize =======================
__global__ void finalize_kernel(const float* __restrict__ sigma,
                                float* __restrict__ out, int nobs) {
    double s2 = (double)sigma[0] * (double)sigma[0];
    double E = g_acc[0] / (2.0 * s2) + 0.5 * (g_acc[1] + g_acc[2]) +
               (double)nobs * log(s2);
    out[0] = (float)E;
}

extern "C" void kernel_launch(void* const* d_in, const int* in_sizes, int n_in,
                              void* d_out, int out_size) {
    const float* vals  = (const float*)d_in[0];
    const int*   rows  = (const int*)d_in[1];
    const int*   cols  = (const int*)d_in[2];
    const float* U     = (const float*)d_in[3];
    const float* V     = (const float*)d_in[4];
    const float* sigma = (const float*)d_in[5];
    const float* S_U   = (const float*)d_in[6];
    const float* S_V   = (const float*)d_in[7];
    int nobs = in_sizes[0];
    float* out = (float*)d_out;

    cudaFuncSetAttribute(fused_kernel,
                         cudaFuncAttributeMaxDynamicSharedMemorySize, QSMEM);

    prep_kernel<<<dim3(NDIM / 32, RANK / 32, 2), dim3(32, 32)>>>(V, U);
    fused_kernel<<<dim3(NDIM / BM, 1, 2), QTHREADS, QSMEM>>>(
        S_U, U, S_V, vals, rows, cols, nobs);
    finalize_kernel<<<1, 1>>>(sigma, out, nobs);
}

// round 7
// speedup vs baseline: 1.2644x; 1.2644x over previous
#include <cuda_runtime.h>
#include <cuda_bf16.h>
#include <cstdint>
#include <math.h>

#define NDIM 8192
#define RANK 64
#define BM 128
#define BKC 64
#define KHALF (NDIM / 2)       // 4096
#define NCHH (KHALF / BKC)     // 64 chunks per CTA
#define QTHREADS 256
#define A_TILE (BM * 144)
#define B_TILE (RANK * 144)
#define QSMEM (1024 + 2 * (A_TILE + B_TILE))
#define NCTAS 256

// ---- device scratch (allocation-free rule) ----
__device__ double g_acc[3];                     // [0]=E1, [1]=quad_U, [2]=quad_V
__device__ unsigned int g_done;                 // CTA completion counter
__device__ float  g_Vt[NDIM * RANK];            // V^T fp32 [8192,64]
__device__ __nv_bfloat16 g_Bu[RANK * NDIM];     // U^T bf16 [64,8192] (MMA B)
__device__ __nv_bfloat16 g_Bv[RANK * NDIM];     // V   bf16 [64,8192] (MMA B)
__device__ __nv_bfloat16 g_Ub16[NDIM * RANK];   // U    bf16 [8192,64] (e1)
__device__ __nv_bfloat16 g_Vt16[NDIM * RANK];   // V^T  bf16 [8192,64] (e1)

__device__ __forceinline__ uint32_t smem_u32(const void* p) {
    uint32_t a;
    asm("{ .reg .u64 t; cvta.to.shared.u64 t, %1; cvt.u32.u64 %0, t; }"
        : "=r"(a) : "l"(p));
    return a;
}

// ======================= prep (fused, grid.z selects) =======================
__global__ void prep_kernel(const float* __restrict__ V,
                            const float* __restrict__ U) {
    __shared__ float tile[32][33];
    if (blockIdx.z == 0) {
        int x = blockIdx.x * 32 + threadIdx.x;   // n
        int y = blockIdx.y * 32 + threadIdx.y;   // r
        float v = V[(size_t)y * NDIM + x];
        tile[threadIdx.y][threadIdx.x] = v;
        g_Bv[(size_t)y * NDIM + x] = __float2bfloat16(v);
        __syncthreads();
        int n = blockIdx.x * 32 + threadIdx.y;
        int r = blockIdx.y * 32 + threadIdx.x;
        float tv = tile[threadIdx.x][threadIdx.y];
        g_Vt[(size_t)n * RANK + r] = tv;
        g_Vt16[(size_t)n * RANK + r] = __float2bfloat16(tv);
        if (blockIdx.x == 0 && blockIdx.y == 0 && threadIdx.y == 0 &&
            threadIdx.x < 3)
            g_acc[threadIdx.x] = 0.0;
    } else {
        int i0 = blockIdx.x * 32, r0 = blockIdx.y * 32;
        float u = U[(size_t)(i0 + threadIdx.y) * RANK + r0 + threadIdx.x];
        tile[threadIdx.y][threadIdx.x] = u;
        g_Ub16[(size_t)(i0 + threadIdx.y) * RANK + r0 + threadIdx.x] =
            __float2bfloat16(u);
        __syncthreads();
        g_Bu[(size_t)(r0 + threadIdx.y) * NDIM + i0 + threadIdx.x] =
            __float2bfloat16(tile[threadIdx.x][threadIdx.y]);
    }
}

// ============== fused quad (HMMA bf16) + e1 + finalize ==============
// 256 threads, 8 warps: warp wid owns M rows wid*16..+15, full N=64.
// K split across grid.y (2 halves). 2 CTAs/SM. 2 smem buffers, 1 sync/chunk.
__global__ __launch_bounds__(QTHREADS, 2) void fused_kernel(
    const float* __restrict__ S_U, const float* __restrict__ U,
    const float* __restrict__ S_V, const float* __restrict__ vals,
    const int* __restrict__ rows, const int* __restrict__ cols,
    const float* __restrict__ sigma, float* __restrict__ out, int nobs) {
    extern __shared__ char dynsmem[];
    __shared__ float wsum[QTHREADS / 32];
    __shared__ float esum[QTHREADS / 32];

    const int t = threadIdx.x;
    const int wid = t >> 5, lane = t & 31;

    const float* S;
    const __nv_bfloat16* Bg;
    const float* Xf;
    int slot;
    if (blockIdx.z == 0) { S = S_U; Bg = g_Bu; Xf = U;    slot = 1; }
    else                 { S = S_V; Bg = g_Bv; Xf = g_Vt; slot = 2; }
    const int i0 = blockIdx.x * BM;
    const size_t kbase = (size_t)blockIdx.y * KHALF;
    const int ctaid = blockIdx.x + 64 * blockIdx.y + 128 * blockIdx.z; // 0..255

    uint32_t base = (smem_u32(dynsmem) + 1023u) & ~1023u;
    uint32_t buf0 = base;
    uint32_t buf1 = base + (A_TILE + B_TILE);

    // ---- staging: A 8 passes x float4; B 2 passes x uint4 ----
    uint32_t a_sts[8];
    const float* a_ldg[8];
    #pragma unroll
    for (int p = 0; p < 8; p++) {
        int flat = p * QTHREADS + t;
        int row = flat >> 4;
        int c = (flat & 15) * 4;
        a_sts[p] = row * 144 + (flat & 15) * 8;
        a_ldg[p] = S + (size_t)(i0 + row) * NDIM + kbase + c;
    }
    uint32_t b_sts[2];
    const __nv_bfloat16* b_ldg[2];
    #pragma unroll
    for (int p = 0; p < 2; p++) {
        int flat = p * QTHREADS + t;
        int row = flat >> 3;
        int c16 = (flat & 7) * 16;
        b_sts[p] = row * 144 + c16;
        b_ldg[p] = Bg + (size_t)row * NDIM + kbase + c16 / 2;
    }

    const uint32_t a_lm = (uint32_t)(wid * 16 + (lane & 15)) * 144 + (lane & 16);
    const uint32_t b_lm = (uint32_t)((lane & 7) + ((lane & 16) >> 1)) * 144 +
                          ((lane & 8) << 1);

    float acc[8][4];
    #pragma unroll
    for (int tn = 0; tn < 8; tn++)
        #pragma unroll
        for (int q = 0; q < 4; q++) acc[tn][q] = 0.f;

    float e1sum = 0.f;
    float4 rA[8];
    uint4  rB[2];

#define LOADC(k0) do {                                                        \
    _Pragma("unroll") for (int p = 0; p < 8; p++)                             \
        rA[p] = __ldcs((const float4*)(a_ldg[p] + (k0)));                     \
    _Pragma("unroll") for (int p = 0; p < 2; p++)                             \
        rB[p] = *(const uint4*)(b_ldg[p] + (k0));                             \
} while (0)

#define STOREC(buf) do {                                                      \
    _Pragma("unroll") for (int p = 0; p < 8; p++) {                           \
        uint32_t lo, hi;                                                      \
        asm("cvt.rn.bf16x2.f32 %0, %1, %2;" : "=r"(lo)                        \
            : "f"(rA[p].y), "f"(rA[p].x));                                    \
        asm("cvt.rn.bf16x2.f32 %0, %1, %2;" : "=r"(hi)                        \
            : "f"(rA[p].w), "f"(rA[p].z));                                    \
        asm volatile("st.shared.v2.b32 [%0], {%1, %2};"                       \
                     :: "r"((buf) + a_sts[p]), "r"(lo), "r"(hi));             \
    }                                                                         \
    _Pragma("unroll") for (int p = 0; p < 2; p++)                             \
        asm volatile("st.shared.v4.b32 [%0], {%1, %2, %3, %4};"               \
                     :: "r"((buf) + A_TILE + b_sts[p]), "r"(rB[p].x),         \
                        "r"(rB[p].y), "r"(rB[p].z), "r"(rB[p].w));            \
} while (0)

#define COMPUTE(buf) do {                                                     \
    uint32_t ab = (buf), bb = (buf) + A_TILE;                                 \
    _Pragma("unroll") for (int s = 0; s < 4; s++) {                           \
        uint32_t a[4];                                                        \
        asm volatile("ldmatrix.sync.aligned.m8n8.x4.shared.b16 "              \
                     "{%0,%1,%2,%3}, [%4];"                                   \
                     : "=r"(a[0]), "=r"(a[1]), "=r"(a[2]), "=r"(a[3])         \
                     : "r"(ab + a_lm + s * 32));                              \
        uint32_t b[4][4];                                                     \
        _Pragma("unroll") for (int j = 0; j < 4; j++)                         \
            asm volatile("ldmatrix.sync.aligned.m8n8.x4.shared.b16 "          \
                         "{%0,%1,%2,%3}, [%4];"                               \
                         : "=r"(b[j][0]), "=r"(b[j][1]),                      \
                           "=r"(b[j][2]), "=r"(b[j][3])                       \
                         : "r"(bb + b_lm + j * (16 * 144) + s * 32));         \
        _Pragma("unroll") for (int tn = 0; tn < 8; tn++)                      \
            asm volatile("mma.sync.aligned.m16n8k16.row.col.f32.bf16.bf16.f32 " \
                         "{%0,%1,%2,%3}, {%4,%5,%6,%7}, {%8,%9}, "            \
                         "{%0,%1,%2,%3};"                                     \
                         : "+f"(acc[tn][0]), "+f"(acc[tn][1]),                \
                           "+f"(acc[tn][2]), "+f"(acc[tn][3])                 \
                         : "r"(a[0]), "r"(a[1]), "r"(a[2]), "r"(a[3]),        \
                           "r"(b[tn >> 1][(tn & 1) * 2]),                     \
                           "r"(b[tn >> 1][(tn & 1) * 2 + 1]));                \
    }                                                                         \
} while (0)

#define E1_STEP(j) do {                                                       \
    int idx = ctaid * 4096 + (j) * QTHREADS + t;                              \
    if (idx < nobs) {                                                         \
        int r = rows[idx], c = cols[idx];                                     \
        float vv = vals[idx];                                                 \
        const uint4* u4 = (const uint4*)(g_Ub16 + (size_t)r * RANK);          \
        const uint4* v4 = (const uint4*)(g_Vt16 + (size_t)c * RANK);          \
        float s = 0.f;                                                        \
        _Pragma("unroll") for (int q = 0; q < 8; q++) {                       \
            uint4 ua = u4[q];                                                 \
            uint4 vb = v4[q];                                                 \
            const uint32_t* up = &ua.x;                                       \
            const uint32_t* vp = &vb.x;                                       \
            _Pragma("unroll") for (int h = 0; h < 4; h++) {                   \
                float2 fu = __bfloat1622float2(                               \
                    *(const __nv_bfloat162*)&up[h]);                          \
                float2 fv = __bfloat1622float2(                               \
                    *(const __nv_bfloat162*)&vp[h]);                          \
                s = fmaf(fu.x, fv.x, s);                                      \
                s = fmaf(fu.y, fv.y, s);                                      \
            }                                                                 \
        }                                                                     \
        float d = vv - s;                                                     \
        e1sum = fmaf(d, d, e1sum);                                            \
    }                                                                         \
} while (0)

    // prologue
    LOADC(0);
    STOREC(buf0);
    __syncthreads();

    // steady: per chunk — load(cc+1), compute(cc), store(cc+1), ONE sync
    for (int cc = 0; cc < NCHH; cc++) {
        uint32_t cur = (cc & 1) ? buf1 : buf0;
        uint32_t nxt = (cc & 1) ? buf0 : buf1;
        if (cc + 1 < NCHH) LOADC((size_t)(cc + 1) * BKC);
        if ((cc & 3) == 0) E1_STEP(cc >> 2);     // 16 obs per thread
        COMPUTE(cur);
        if (cc + 1 < NCHH) {
            STOREC(nxt);
            __syncthreads();
        }
    }

    // quad epilogue: partial = sum of D[row][n] * X[row][n]
    const int g = lane >> 2, tg = lane & 3;
    const int r0 = i0 + wid * 16 + g;
    float partial = 0.f;
    #pragma unroll
    for (int tn = 0; tn < 8; tn++) {
        int n = tn * 8 + 2 * tg;
        float2 x0 = *(const float2*)(Xf + (size_t)r0 * RANK + n);
        float2 x1 = *(const float2*)(Xf + (size_t)(r0 + 8) * RANK + n);
        partial = fmaf(acc[tn][0], x0.x, partial);
        partial = fmaf(acc[tn][1], x0.y, partial);
        partial = fmaf(acc[tn][2], x1.x, partial);
        partial = fmaf(acc[tn][3], x1.y, partial);
    }
    #pragma unroll
    for (int o = 16; o; o >>= 1) {
        partial += __shfl_xor_sync(0xffffffffu, partial, o);
        e1sum   += __shfl_xor_sync(0xffffffffu, e1sum, o);
    }
    if (lane == 0) { wsum[wid] = partial; esum[wid] = e1sum; }
    __syncthreads();
    if (t == 0) {
        float s = 0.f, e = 0.f;
        #pragma unroll
        for (int i = 0; i < QTHREADS / 32; i++) { s += wsum[i]; e += esum[i]; }
        atomicAdd(&g_acc[slot], (double)s);
        atomicAdd(&g_acc[0], (double)e);
        __threadfence();
        unsigned int old = atomicAdd(&g_done, 1u);
        if (old == NCTAS - 1) {                  // last CTA finalizes
            __threadfence();
            g_done = 0;                          // reset for next replay
            double e0 = atomicAdd(&g_acc[0], 0.0);
            double e1 = atomicAdd(&g_acc[1], 0.0);
            double e2 = atomicAdd(&g_acc[2], 0.0);
            double s2 = (double)sigma[0] * (double)sigma[0];
            double E = e0 / (2.0 * s2) + 0.5 * (e1 + e2) +
                       (double)nobs * log(s2);
            out[0] = (float)E;
        }
    }
#undef LOADC
#undef STOREC
#undef COMPUTE
#undef E1_STEP
}

extern "C" void kernel_launch(void* const* d_in, const int* in_sizes, int n_in,
                              void* d_out, int out_size) {
    const float* vals  = (const float*)d_in[0];
    const int*   rows  = (const int*)d_in[1];
    const int*   cols  = (const int*)d_in[2];
    const float* U     = (const float*)d_in[3];
    const float* V     = (const float*)d_in[4];
    const float* sigma = (const float*)d_in[5];
    const float* S_U   = (const float*)d_in[6];
    const float* S_V   = (const float*)d_in[7];
    int nobs = in_sizes[0];
    float* out = (float*)d_out;

    cudaFuncSetAttribute(fused_kernel,
                         cudaFuncAttributeMaxDynamicSharedMemorySize, QSMEM);

    prep_kernel<<<dim3(NDIM / 32, RANK / 32, 2), dim3(32, 32)>>>(V, U);
    fused_kernel<<<dim3(NDIM / BM, 2, 2), QTHREADS, QSMEM>>>(
        S_U, U, S_V, vals, rows, cols, sigma, out, nobs);
}